// round 5
// baseline (speedup 1.0000x reference)
#include <cuda_runtime.h>

// DRP_LAYER: 2D DRP-FDTD, 3 steps, B=2, N=2048.
// R5: smem-tiled fast path, x4 row coarsening, block = 128 cols x 8 rows.

#define NN   2048
#define BB   2
#define CFLc 0.35f

#define ES   (NN + 1)
#define HXS  (NN)
#define HYS  (NN - 1)
#define ESZ  ((NN + 1) * (NN + 1))
#define HXSZ ((NN - 1) * NN)
#define HYSZ (NN * (NN - 1))

__device__ float g_coef[2];   // [0]=u = 0.25*beta - 0.1*gamma, [1]=delta

__global__ void coef_kernel(const float* __restrict__ beta,
                            const float* __restrict__ delta,
                            const float* __restrict__ gamma) {
    g_coef[0] = 0.25f * beta[0] - 0.1f * gamma[0];
    g_coef[1] = delta[0];
}

#define KF0 (-11.0f/6.0f)
#define KF1 (3.0f)
#define KF2 (-1.5f)
#define KF3 (1.0f/3.0f)
#define KB0 (-1.0f/3.0f)
#define KB1 (1.5f)
#define KB2 (-3.0f)
#define KB3 (11.0f/6.0f)

// ---------------------------------------------------------------------------
// Ampere: E_out = E + CFL*(s1 - s2). Block (128,2) -> tile 128 cols x 8 rows.
// Thread (tx,ty) computes rows li = ty*4 + q (q=0..3), col tx.
// ---------------------------------------------------------------------------
#define HY_R 11
#define HY_C 136
#define HX_R 16
#define HX_C 132

__global__ __launch_bounds__(256, 4) void amper_kernel(
    const float* __restrict__ E, const float* __restrict__ Hx,
    const float* __restrict__ Hy, float* __restrict__ Eo)
{
    __shared__ float HyT[HY_R][HY_C];
    __shared__ float HxT[HX_R][HX_C];

    const int jb = blockIdx.x * 128;
    const int R0 = blockIdx.y * 8;
    const int tx = threadIdx.x;
    const int ty = threadIdx.y;
    const int tid = ty * 128 + tx;
    const int b  = blockIdx.z;

    const float* __restrict__ e  = E  + (size_t)b * ESZ;
    const float* __restrict__ hx = Hx + (size_t)b * HXSZ;
    const float* __restrict__ hy = Hy + (size_t)b * HYSZ;
    float* __restrict__ eo = Eo + (size_t)b * ESZ;

    const float u  = g_coef[0];
    const float dl = g_coef[1];
    const float c01 = u + dl - 0.5f;
    const float c11 = -2.0f * dl;
    const float c21 = dl + 0.5f - u;
    const float cKF = c21 + KF0;
    const float cKB = u + KB3;

#define HXg(r,c) hx[(r) * HXS + (c)]
#define HYg(r,c) hy[(r) * HYS + (c)]

    const bool fast = (R0 >= 8) && (R0 + 7 <= NN - 5) &&
                      (jb >= 128) && (jb + 127 <= NN - 5);

    if (fast) {
        // Stage tiles: HyT rows R0-2..R0+8, cols jb-5..jb+130
        for (int idx = tid; idx < HY_R * HY_C; idx += 256) {
            const int r = idx / HY_C, c = idx % HY_C;
            HyT[r][c] = HYg(R0 - 2 + r, jb - 5 + c);
        }
        // HxT rows R0-5..R0+10, cols jb-2..jb+129
        for (int idx = tid; idx < HX_R * HX_C; idx += 256) {
            const int r = idx / HX_C, c = idx % HX_C;
            HxT[r][c] = HXg(R0 - 5 + r, jb - 2 + c);
        }
        __syncthreads();

        // Hy(i+dr, j+dc) -> HyT[li+2+dr][tx+5+dc]
        // Hx(i+dr, j+dc) -> HxT[li+5+dr][tx+2+dc]
#define HYs(dr,dc) HyT[li + 2 + (dr)][tx + 5 + (dc)]
#define HXs(dr,dc) HxT[li + 5 + (dr)][tx + 2 + (dc)]

#pragma unroll
        for (int q = 0; q < 4; q++) {
            const int li = ty * 4 + q;
            float s1 = -u  * HYs(-2,-2) + u * HYs(-2,0)
                     + c01 * HYs(-1,-2) + c11 * HYs(-1,-1) + cKF * HYs(-1,0)
                     + KF1 * HYs(-1,1) + KF2 * HYs(-1,2) + KF3 * HYs(-1,3)
                     + KB0 * HYs(0,-5) + KB1 * HYs(0,-4) + KB2 * HYs(0,-3)
                     + cKB * HYs(0,-2) - u * HYs(0,0)
                     - u  * HYs(1,-2) + u * HYs(1,0);
            float s2 = KB0 * HXs(-5,0) + KB1 * HXs(-4,0) + KB2 * HXs(-3,0)
                     - u  * HXs(-2,-2) + c01 * HXs(-2,-1) + cKB * HXs(-2,0) - u * HXs(-2,1)
                     + c11 * HXs(-1,-1)
                     + u   * HXs(0,-2) + cKF * HXs(0,-1) - u * HXs(0,0) + u * HXs(0,1)
                     + KF1 * HXs(1,-1) + KF2 * HXs(2,-1) + KF3 * HXs(3,-1);
            const int idx = (R0 + li) * ES + jb + tx;
            eo[idx] = e[idx] + CFLc * (s1 - s2);
        }
#undef HYs
#undef HXs
        return;
    }

    // ---- generic path (edges) ----
    const int j = jb + tx;
    if (j > NN) return;
#pragma unroll
    for (int q = 0; q < 4; q++) {
        const int i = R0 + ty * 4 + q;
        if (i > NN) break;

        const bool iin = (i >= 2) && (i <= NN - 2);
        const bool jin = (j >= 2) && (j <= NN - 2);

        float s1 = 0.0f;
        if (iin && jin) {
            s1 += -u  * HYg(i-2, j-2) + u   * HYg(i-2, j)
                + c01 * HYg(i-1, j-2) + c11 * HYg(i-1, j-1) + c21 * HYg(i-1, j)
                + u   * HYg(i  , j-2) - u   * HYg(i  , j)
                - u   * HYg(i+1, j-2) + u   * HYg(i+1, j);
        }
        if (i >= 1 && j <= NN - 5)
            s1 += KF0*HYg(i-1, j) + KF1*HYg(i-1, j+1) + KF2*HYg(i-1, j+2) + KF3*HYg(i-1, j+3);
        if (i <= NN - 1 && j >= 5)
            s1 += KB0*HYg(i, j-5) + KB1*HYg(i, j-4) + KB2*HYg(i, j-3) + KB3*HYg(i, j-2);
        if (iin && (j == 1 || j == 2))
            s1 += -HYg(i-1, j-1) + 3.0f*HYg(i-1, j) - 3.0f*HYg(i-1, j+1) + HYg(i-1, j+2);
        if (iin && (j == NN-2 || j == NN-1))
            s1 += HYg(i, j-4) - 3.0f*HYg(i, j-3) + 3.0f*HYg(i, j-2) - HYg(i, j-1);

        float s2 = 0.0f;
        if (iin && jin) {
            s2 += -u  * HXg(i-2, j-2) + c01 * HXg(i-2, j-1) + u * HXg(i-2, j) - u * HXg(i-2, j+1)
                + c11 * HXg(i-1, j-1)
                + u   * HXg(i  , j-2) + c21 * HXg(i  , j-1) - u * HXg(i  , j) + u * HXg(i  , j+1);
        }
        if (i <= NN - 5 && j >= 1)
            s2 += KF0*HXg(i, j-1) + KF1*HXg(i+1, j-1) + KF2*HXg(i+2, j-1) + KF3*HXg(i+3, j-1);
        if (i >= 5 && j <= NN - 1)
            s2 += KB0*HXg(i-5, j) + KB1*HXg(i-4, j) + KB2*HXg(i-3, j) + KB3*HXg(i-2, j);
        if ((i == 1 || i == 2) && jin)
            s2 += -HXg(i-1, j-1) + 3.0f*HXg(i, j-1) - 3.0f*HXg(i+1, j-1) + HXg(i+2, j-1);
        if ((i == NN-2 || i == NN-1) && jin)
            s2 += HXg(i-4, j) - 3.0f*HXg(i-3, j) + 3.0f*HXg(i-2, j) - HXg(i-1, j);

        const int idx = i * ES + j;
        eo[idx] = e[idx] + CFLc * (s1 - s2);
    }
#undef HXg
#undef HYg
}

// ---------------------------------------------------------------------------
// Faraday: Hx_out = Hx - CFL*s3 ; Hy_out = Hy + CFL*s4
// Block (128,2) -> tile 128 cols x 8 rows, E staged in smem.
// ---------------------------------------------------------------------------
#define ET_R 12
#define ET_C 133

__global__ __launch_bounds__(256, 4) void faraday_kernel(
    const float* __restrict__ E, const float* __restrict__ Hx,
    const float* __restrict__ Hy, float* __restrict__ Hxo,
    float* __restrict__ Hyo)
{
    __shared__ float ET[ET_R][ET_C];

    const int jb = blockIdx.x * 128;
    const int R0 = blockIdx.y * 8;
    const int tx = threadIdx.x;
    const int ty = threadIdx.y;
    const int tid = ty * 128 + tx;
    const int b  = blockIdx.z;

    const float* __restrict__ e  = E  + (size_t)b * ESZ;
    const float* __restrict__ hx = Hx + (size_t)b * HXSZ;
    const float* __restrict__ hy = Hy + (size_t)b * HYSZ;
    float* __restrict__ hxo = Hxo + (size_t)b * HXSZ;
    float* __restrict__ hyo = Hyo + (size_t)b * HYSZ;

    const float u  = g_coef[0];
    const float dl = g_coef[1];
    const float c01 = u + dl - 0.5f;
    const float c11 = -2.0f * dl;
    const float c21 = dl + 0.5f - u;

#define EEg(r,c) e[(r) * ES + (c)]

    const bool fast = (R0 >= 8) && (R0 + 7 <= NN - 4) &&
                      (jb >= 128) && (jb + 127 <= NN - 4);

    if (fast) {
        // ET rows R0-1..R0+10, cols jb-1..jb+131
        for (int idx = tid; idx < ET_R * ET_C; idx += 256) {
            const int r = idx / ET_C, c = idx % ET_C;
            ET[r][c] = EEg(R0 - 1 + r, jb - 1 + c);
        }
        __syncthreads();

        // E(i+dr, j+dc) -> ET[li+1+dr][tx+1+dc]
#define EEs(dr,dc) ET[li + 1 + (dr)][tx + 1 + (dc)]

#pragma unroll
        for (int q = 0; q < 4; q++) {
            const int li = ty * 4 + q;
            const int i = R0 + li;
            const int j = jb + tx;
            float s3 = 0.5f * EEs(-1,1)
                     - u * EEs(0,-1) + c01 * EEs(0,0) + (u - 2.0f) * EEs(0,1) - u * EEs(0,2)
                     + (c11 - 1.5f) * EEs(1,0) + 1.5f * EEs(1,1)
                     + u * EEs(2,-1) + (c21 + 2.0f) * EEs(2,0) - u * EEs(2,1) + u * EEs(2,2)
                     - 0.5f * EEs(3,0);
            hxo[i * HXS + j] = hx[i * HXS + j] - CFLc * s3;

            float s4 = -u * EEs(-1,0) + u * EEs(-1,2)
                     + c01 * EEs(0,0) + (c11 - 1.5f) * EEs(0,1)
                     + (c21 + 2.0f) * EEs(0,2) - 0.5f * EEs(0,3)
                     + 0.5f * EEs(1,-1) + (u - 2.0f) * EEs(1,0) + 1.5f * EEs(1,1) - u * EEs(1,2)
                     - u * EEs(2,0) + u * EEs(2,2);
            hyo[i * HYS + j] = hy[i * HYS + j] + CFLc * s4;
        }
#undef EEs
        return;
    }

    // ---- generic path (edges) ----
    const int j = jb + tx;
    if (j >= NN) return;
#pragma unroll
    for (int q = 0; q < 4; q++) {
        const int i = R0 + ty * 4 + q;
        if (i >= NN) break;

        if (i <= NN - 2) {
            float s3 = 0.0f;
            if (j >= 1 && j <= NN - 2) {
                s3 += -u  * EEg(i  , j-1) + c01 * EEg(i  , j) + u * EEg(i  , j+1) - u * EEg(i  , j+2)
                    + c11 * EEg(i+1, j)
                    + u   * EEg(i+2, j-1) + c21 * EEg(i+2, j) - u * EEg(i+2, j+1) + u * EEg(i+2, j+2);
            }
            if (i <= NN - 4)
                s3 += -1.5f * EEg(i+1, j) + 2.0f * EEg(i+2, j) - 0.5f * EEg(i+3, j);
            if (i >= 2)
                s3 +=  0.5f * EEg(i-1, j+1) - 2.0f * EEg(i, j+1) + 1.5f * EEg(i+1, j+1);
            hxo[i * HXS + j] = hx[i * HXS + j] - CFLc * s3;
        }

        if (j <= NN - 2) {
            float s4 = 0.0f;
            if (i >= 1 && i <= NN - 2) {
                s4 += -u  * EEg(i-1, j) + u * EEg(i-1, j+2)
                    + c01 * EEg(i  , j) + c11 * EEg(i, j+1) + c21 * EEg(i, j+2)
                    + u   * EEg(i+1, j) - u * EEg(i+1, j+2)
                    - u   * EEg(i+2, j) + u * EEg(i+2, j+2);
            }
            if (j <= NN - 4)
                s4 += -1.5f * EEg(i, j+1) + 2.0f * EEg(i, j+2) - 0.5f * EEg(i, j+3);
            if (j >= 2)
                s4 +=  0.5f * EEg(i+1, j-1) - 2.0f * EEg(i+1, j) + 1.5f * EEg(i+1, j+1);
            hyo[i * HYS + j] = hy[i * HYS + j] + CFLc * s4;
        }
    }
#undef EEg
}

// ---------------------------------------------------------------------------
extern "C" void kernel_launch(void* const* d_in, const int* in_sizes, int n_in,
                              void* d_out, int out_size)
{
    const float* E0    = (const float*)d_in[0];
    const float* Hx0   = (const float*)d_in[1];
    const float* Hy0   = (const float*)d_in[2];
    const float* beta  = (const float*)d_in[3];
    const float* delta = (const float*)d_in[4];
    const float* gamma = (const float*)d_in[5];

    float* out = (float*)d_out;
    const size_t esz  = (size_t)BB * ESZ;
    const size_t hxsz = (size_t)BB * HXSZ;
    const size_t hysz = (size_t)BB * HYSZ;

    float* E2  = out;
    float* Hx2 = E2  + esz;
    float* Hy2 = Hx2 + hxsz;
    float* E3  = Hy2 + hysz;
    float* Hx3 = E3  + esz;
    float* Hy3 = Hx3 + hxsz;
    float* E4  = Hy3 + hysz;
    float* Hx4 = E4  + esz;
    float* Hy4 = Hx4 + hxsz;

    coef_kernel<<<1, 1>>>(beta, delta, gamma);

    dim3 blk(128, 2, 1);
    dim3 gE((NN + 1 + 127) / 128, (NN + 1 + 7) / 8, BB);   // 17 x 257 x 2
    dim3 gH((NN + 127) / 128, (NN + 7) / 8, BB);           // 16 x 256 x 2

    amper_kernel  <<<gE, blk>>>(E0, Hx0, Hy0, E2);
    faraday_kernel<<<gH, blk>>>(E2, Hx0, Hy0, Hx2, Hy2);

    amper_kernel  <<<gE, blk>>>(E2, Hx2, Hy2, E3);
    faraday_kernel<<<gH, blk>>>(E3, Hx2, Hy2, Hx3, Hy3);

    amper_kernel  <<<gE, blk>>>(E3, Hx3, Hy3, E4);
    faraday_kernel<<<gH, blk>>>(E4, Hx3, Hy3, Hx4, Hy4);
}

// round 6
// speedup vs baseline: 1.3995x; 1.3995x over previous
#include <cuda_runtime.h>

// DRP_LAYER: 2D DRP-FDTD, 3 steps, B=2, N=2048.
// R6: float2-vectorized column pairs; E/Hy kept in even-stride padded
// ping-pong scratch (__device__ globals) so all vector loads are 8B-aligned.

#define NN   2048
#define BB   2
#define CFLc 0.35f

#define ES   (NN + 1)              // 2049 d_out E stride (odd -> scalar stores)
#define HXS  (NN)                  // 2048
#define HYS  (NN - 1)              // 2047 d_out Hy stride (odd -> scalar stores)
#define ESZ  ((NN + 1) * (NN + 1))
#define HXSZ ((NN - 1) * NN)
#define HYSZ (NN * (NN - 1))

#define PE   2052                  // padded E stride (even, %4==0)
#define PHY  2048                  // padded Hy stride

// Padded ping-pong state (static device memory; allocation-free).
__device__ __align__(16) float g_EpadA[BB * (NN + 1) * PE];
__device__ __align__(16) float g_EpadB[BB * (NN + 1) * PE];
__device__ __align__(16) float g_HyA[BB * NN * PHY];
__device__ __align__(16) float g_HyB[BB * NN * PHY];

__device__ float g_coef[2];   // [0]=u = 0.25*beta - 0.1*gamma, [1]=delta

__global__ void coef_kernel(const float* __restrict__ beta,
                            const float* __restrict__ delta,
                            const float* __restrict__ gamma) {
    g_coef[0] = 0.25f * beta[0] - 0.1f * gamma[0];
    g_coef[1] = delta[0];
}

__global__ void repackE_kernel(const float* __restrict__ E0) {
    int idx = blockIdx.x * blockDim.x + threadIdx.x;
    const int tot = BB * ES * ES;
    if (idx >= tot) return;
    int b = idx / (ES * ES);
    int r = (idx / ES) % ES;
    int c = idx % ES;
    g_EpadA[((size_t)b * ES + r) * PE + c] = E0[idx];
}

__global__ void repackHy_kernel(const float* __restrict__ Hy0) {
    int idx = blockIdx.x * blockDim.x + threadIdx.x;
    const int tot = BB * NN * HYS;
    if (idx >= tot) return;
    int b = idx / (NN * HYS);
    int r = (idx / HYS) % NN;
    int c = idx % HYS;
    g_HyA[((size_t)b * NN + r) * PHY + c] = Hy0[idx];
}

#define KF0 (-11.0f/6.0f)
#define KF1 (3.0f)
#define KF2 (-1.5f)
#define KF3 (1.0f/3.0f)
#define KB0 (-1.0f/3.0f)
#define KB1 (1.5f)
#define KB2 (-3.0f)
#define KB3 (11.0f/6.0f)

// Load n float2 (2n floats) from base+off (off must be even) into dst[0..2n).
#define LDROW(dst, base, off, n) do {                                      \
    const float2* _p = reinterpret_cast<const float2*>((base) + (off));    \
    _Pragma("unroll")                                                      \
    for (int _k = 0; _k < (n); _k++) {                                     \
        float2 _v = _p[_k]; (dst)[2*_k] = _v.x; (dst)[2*_k+1] = _v.y;      \
    } } while (0)

// ---------------------------------------------------------------------------
// Ampere: E_out = E + CFL*(s1 - s2). Block (64,4): thread handles row
// r = R0+ty, column pair j0 = jb + 2*tx. Block tile: 128 cols x 4 rows.
// Reads: E/Hy from padded buffers, Hx natural.
// Writes: E to d_out (scalar) and padded out (f2).
// ---------------------------------------------------------------------------
__global__ __launch_bounds__(256, 4) void amper_kernel(
    const float* __restrict__ epad_in, const float* __restrict__ Hx,
    const float* __restrict__ hyp_in,
    float* __restrict__ eo_d, float* __restrict__ epad_out)
{
    const int jb = blockIdx.x * 128;
    const int R0 = blockIdx.y * 4;
    const int tx = threadIdx.x;
    const int r  = R0 + threadIdx.y;
    const int j0 = jb + 2 * tx;
    const int b  = blockIdx.z;

    const float* __restrict__ ein = epad_in + (size_t)b * ES * PE;
    const float* __restrict__ hx  = Hx      + (size_t)b * HXSZ;
    const float* __restrict__ hyp = hyp_in  + (size_t)b * NN * PHY;
    float* __restrict__ eo  = eo_d     + (size_t)b * ESZ;
    float* __restrict__ epo = epad_out + (size_t)b * ES * PE;

    const float u  = g_coef[0];
    const float dl = g_coef[1];
    const float c01 = u + dl - 0.5f;
    const float c11 = -2.0f * dl;
    const float c21 = dl + 0.5f - u;
    const float cKF = c21 + KF0;
    const float cKB = u + KB3;

    const bool fast = (R0 >= 8) && (R0 + 3 <= NN - 5) &&
                      (jb >= 128) && (jb + 127 <= NN - 5);

    if (fast) {
        // ---- s1 from padded Hy ----
        float ym2[4], ym1[8], y0[8], yp1[4];
        LDROW(ym2, hyp, (r-2) * PHY + (j0-2), 2);
        LDROW(ym1, hyp, (r-1) * PHY + (j0-2), 4);
        LDROW(y0 , hyp, (r  ) * PHY + (j0-6), 4);
        LDROW(yp1, hyp, (r+1) * PHY + (j0-2), 2);

        float s1v[2];
#pragma unroll
        for (int q = 0; q < 2; q++) {
            s1v[q] = -u * ym2[q] + u * ym2[q+2]
                   + c01 * ym1[q] + c11 * ym1[q+1] + cKF * ym1[q+2]
                   + KF1 * ym1[q+3] + KF2 * ym1[q+4] + KF3 * ym1[q+5]
                   + KB0 * y0[q+1] + KB1 * y0[q+2] + KB2 * y0[q+3]
                   + cKB * y0[q+4] - u * y0[q+6]
                   - u * yp1[q] + u * yp1[q+2];
        }

        // ---- s2 from Hx (natural even stride) ----
        float xm5[2], xm4[2], xm3[2], xm2[6], xm1[4], x0[6], xp1[4], xp2[4], xp3[4];
        LDROW(xm5, hx, (r-5) * HXS + j0, 1);
        LDROW(xm4, hx, (r-4) * HXS + j0, 1);
        LDROW(xm3, hx, (r-3) * HXS + j0, 1);
        LDROW(xm2, hx, (r-2) * HXS + (j0-2), 3);
        LDROW(xm1, hx, (r-1) * HXS + (j0-2), 2);
        LDROW(x0 , hx, (r  ) * HXS + (j0-2), 3);
        LDROW(xp1, hx, (r+1) * HXS + (j0-2), 2);
        LDROW(xp2, hx, (r+2) * HXS + (j0-2), 2);
        LDROW(xp3, hx, (r+3) * HXS + (j0-2), 2);

        float2 ep = *reinterpret_cast<const float2*>(ein + (size_t)r * PE + j0);
        float o[2];
#pragma unroll
        for (int q = 0; q < 2; q++) {
            float s2 = KB0 * xm5[q] + KB1 * xm4[q] + KB2 * xm3[q]
                     - u * xm2[q] + c01 * xm2[q+1] + cKB * xm2[q+2] - u * xm2[q+3]
                     + c11 * xm1[q+1]
                     + u * x0[q] + cKF * x0[q+1] - u * x0[q+2] + u * x0[q+3]
                     + KF1 * xp1[q+1] + KF2 * xp2[q+1] + KF3 * xp3[q+1];
            o[q] = (q == 0 ? ep.x : ep.y) + CFLc * (s1v[q] - s2);
        }
        eo[(size_t)r * ES + j0]     = o[0];
        eo[(size_t)r * ES + j0 + 1] = o[1];
        *reinterpret_cast<float2*>(epo + (size_t)r * PE + j0) = make_float2(o[0], o[1]);
        return;
    }

    // ---- generic path (edges) ----
#define HXg(rr,cc) hx[(rr) * HXS + (cc)]
#define HYg(rr,cc) hyp[(rr) * PHY + (cc)]
    if (r > NN) return;
    const int i = r;
#pragma unroll
    for (int q = 0; q < 2; q++) {
        const int j = j0 + q;
        if (j > NN) break;

        const bool iin = (i >= 2) && (i <= NN - 2);
        const bool jin = (j >= 2) && (j <= NN - 2);

        float s1 = 0.0f;
        if (iin && jin) {
            s1 += -u  * HYg(i-2, j-2) + u   * HYg(i-2, j)
                + c01 * HYg(i-1, j-2) + c11 * HYg(i-1, j-1) + c21 * HYg(i-1, j)
                + u   * HYg(i  , j-2) - u   * HYg(i  , j)
                - u   * HYg(i+1, j-2) + u   * HYg(i+1, j);
        }
        if (i >= 1 && j <= NN - 5)
            s1 += KF0*HYg(i-1, j) + KF1*HYg(i-1, j+1) + KF2*HYg(i-1, j+2) + KF3*HYg(i-1, j+3);
        if (i <= NN - 1 && j >= 5)
            s1 += KB0*HYg(i, j-5) + KB1*HYg(i, j-4) + KB2*HYg(i, j-3) + KB3*HYg(i, j-2);
        if (iin && (j == 1 || j == 2))
            s1 += -HYg(i-1, j-1) + 3.0f*HYg(i-1, j) - 3.0f*HYg(i-1, j+1) + HYg(i-1, j+2);
        if (iin && (j == NN-2 || j == NN-1))
            s1 += HYg(i, j-4) - 3.0f*HYg(i, j-3) + 3.0f*HYg(i, j-2) - HYg(i, j-1);

        float s2 = 0.0f;
        if (iin && jin) {
            s2 += -u  * HXg(i-2, j-2) + c01 * HXg(i-2, j-1) + u * HXg(i-2, j) - u * HXg(i-2, j+1)
                + c11 * HXg(i-1, j-1)
                + u   * HXg(i  , j-2) + c21 * HXg(i  , j-1) - u * HXg(i  , j) + u * HXg(i  , j+1);
        }
        if (i <= NN - 5 && j >= 1)
            s2 += KF0*HXg(i, j-1) + KF1*HXg(i+1, j-1) + KF2*HXg(i+2, j-1) + KF3*HXg(i+3, j-1);
        if (i >= 5 && j <= NN - 1)
            s2 += KB0*HXg(i-5, j) + KB1*HXg(i-4, j) + KB2*HXg(i-3, j) + KB3*HXg(i-2, j);
        if ((i == 1 || i == 2) && jin)
            s2 += -HXg(i-1, j-1) + 3.0f*HXg(i, j-1) - 3.0f*HXg(i+1, j-1) + HXg(i+2, j-1);
        if ((i == NN-2 || i == NN-1) && jin)
            s2 += HXg(i-4, j) - 3.0f*HXg(i-3, j) + 3.0f*HXg(i-2, j) - HXg(i-1, j);

        const float val = ein[(size_t)i * PE + j] + CFLc * (s1 - s2);
        eo[(size_t)i * ES + j] = val;
        epo[(size_t)i * PE + j] = val;
    }
#undef HXg
#undef HYg
}

// ---------------------------------------------------------------------------
// Faraday: Hx_out = Hx - CFL*s3 ; Hy_out = Hy + CFL*s4
// Block (64,4): row i = R0+ty, pair j0 = jb+2tx. E read from padded buffer.
// ---------------------------------------------------------------------------
__global__ __launch_bounds__(256, 4) void faraday_kernel(
    const float* __restrict__ epad_in, const float* __restrict__ Hx,
    const float* __restrict__ hyp_in,
    float* __restrict__ hxo_d, float* __restrict__ hyo_d,
    float* __restrict__ hyp_out)
{
    const int jb = blockIdx.x * 128;
    const int R0 = blockIdx.y * 4;
    const int tx = threadIdx.x;
    const int i  = R0 + threadIdx.y;
    const int j0 = jb + 2 * tx;
    const int b  = blockIdx.z;

    const float* __restrict__ ein = epad_in + (size_t)b * ES * PE;
    const float* __restrict__ hx  = Hx      + (size_t)b * HXSZ;
    const float* __restrict__ hyp = hyp_in  + (size_t)b * NN * PHY;
    float* __restrict__ hxo = hxo_d   + (size_t)b * HXSZ;
    float* __restrict__ hyo = hyo_d   + (size_t)b * HYSZ;
    float* __restrict__ hpo = hyp_out + (size_t)b * NN * PHY;

    const float u  = g_coef[0];
    const float dl = g_coef[1];
    const float c01 = u + dl - 0.5f;
    const float c11 = -2.0f * dl;
    const float c21 = dl + 0.5f - u;

    const bool fast = (R0 >= 8) && (R0 + 3 <= NN - 4) &&
                      (jb >= 128) && (jb + 127 <= NN - 4);

    if (fast) {
        float em1[4], e0[8], ep1[6], ep2[6], ep3[2];
        LDROW(em1, ein, (i-1) * PE + j0,     2);
        LDROW(e0 , ein, (i  ) * PE + (j0-2), 4);
        LDROW(ep1, ein, (i+1) * PE + (j0-2), 3);
        LDROW(ep2, ein, (i+2) * PE + (j0-2), 3);
        LDROW(ep3, ein, (i+3) * PE + j0,     1);

        float2 hxp = *reinterpret_cast<const float2*>(hx  + (size_t)i * HXS + j0);
        float2 hyv = *reinterpret_cast<const float2*>(hyp + (size_t)i * PHY + j0);

        float ox[2], oy[2];
#pragma unroll
        for (int q = 0; q < 2; q++) {
            float s3 = 0.5f * em1[q+1]
                     - u * e0[q+1] + c01 * e0[q+2] + (u - 2.0f) * e0[q+3] - u * e0[q+4]
                     + (c11 - 1.5f) * ep1[q+2] + 1.5f * ep1[q+3]
                     + u * ep2[q+1] + (c21 + 2.0f) * ep2[q+2] - u * ep2[q+3] + u * ep2[q+4]
                     - 0.5f * ep3[q];
            float s4 = -u * em1[q] + u * em1[q+2]
                     + c01 * e0[q+2] + (c11 - 1.5f) * e0[q+3]
                     + (c21 + 2.0f) * e0[q+4] - 0.5f * e0[q+5]
                     + 0.5f * ep1[q+1] + (u - 2.0f) * ep1[q+2] + 1.5f * ep1[q+3] - u * ep1[q+4]
                     - u * ep2[q+2] + u * ep2[q+4];
            ox[q] = (q == 0 ? hxp.x : hxp.y) - CFLc * s3;
            oy[q] = (q == 0 ? hyv.x : hyv.y) + CFLc * s4;
        }
        *reinterpret_cast<float2*>(hxo + (size_t)i * HXS + j0) = make_float2(ox[0], ox[1]);
        hyo[(size_t)i * HYS + j0]     = oy[0];
        hyo[(size_t)i * HYS + j0 + 1] = oy[1];
        *reinterpret_cast<float2*>(hpo + (size_t)i * PHY + j0) = make_float2(oy[0], oy[1]);
        return;
    }

    // ---- generic path (edges) ----
#define EEg(rr,cc) ein[(rr) * PE + (cc)]
    if (i >= NN) return;
#pragma unroll
    for (int q = 0; q < 2; q++) {
        const int j = j0 + q;
        if (j >= NN) break;

        if (i <= NN - 2) {
            float s3 = 0.0f;
            if (j >= 1 && j <= NN - 2) {
                s3 += -u  * EEg(i  , j-1) + c01 * EEg(i  , j) + u * EEg(i  , j+1) - u * EEg(i  , j+2)
                    + c11 * EEg(i+1, j)
                    + u   * EEg(i+2, j-1) + c21 * EEg(i+2, j) - u * EEg(i+2, j+1) + u * EEg(i+2, j+2);
            }
            if (i <= NN - 4)
                s3 += -1.5f * EEg(i+1, j) + 2.0f * EEg(i+2, j) - 0.5f * EEg(i+3, j);
            if (i >= 2)
                s3 +=  0.5f * EEg(i-1, j+1) - 2.0f * EEg(i, j+1) + 1.5f * EEg(i+1, j+1);
            hxo[(size_t)i * HXS + j] = hx[(size_t)i * HXS + j] - CFLc * s3;
        }

        if (j <= NN - 2) {
            float s4 = 0.0f;
            if (i >= 1 && i <= NN - 2) {
                s4 += -u  * EEg(i-1, j) + u * EEg(i-1, j+2)
                    + c01 * EEg(i  , j) + c11 * EEg(i, j+1) + c21 * EEg(i, j+2)
                    + u   * EEg(i+1, j) - u * EEg(i+1, j+2)
                    - u   * EEg(i+2, j) + u * EEg(i+2, j+2);
            }
            if (j <= NN - 4)
                s4 += -1.5f * EEg(i, j+1) + 2.0f * EEg(i, j+2) - 0.5f * EEg(i, j+3);
            if (j >= 2)
                s4 +=  0.5f * EEg(i+1, j-1) - 2.0f * EEg(i+1, j) + 1.5f * EEg(i+1, j+1);
            const float val = hyp[(size_t)i * PHY + j] + CFLc * s4;
            hyo[(size_t)i * HYS + j] = val;
            hpo[(size_t)i * PHY + j] = val;
        }
    }
#undef EEg
}

// ---------------------------------------------------------------------------
extern "C" void kernel_launch(void* const* d_in, const int* in_sizes, int n_in,
                              void* d_out, int out_size)
{
    const float* E0    = (const float*)d_in[0];
    const float* Hx0   = (const float*)d_in[1];
    const float* Hy0   = (const float*)d_in[2];
    const float* beta  = (const float*)d_in[3];
    const float* delta = (const float*)d_in[4];
    const float* gamma = (const float*)d_in[5];

    float* out = (float*)d_out;
    const size_t esz  = (size_t)BB * ESZ;
    const size_t hxsz = (size_t)BB * HXSZ;
    const size_t hysz = (size_t)BB * HYSZ;

    float* E2  = out;
    float* Hx2 = E2  + esz;
    float* Hy2 = Hx2 + hxsz;
    float* E3  = Hy2 + hysz;
    float* Hx3 = E3  + esz;
    float* Hy3 = Hx3 + hxsz;
    float* E4  = Hy3 + hysz;
    float* Hx4 = E4  + esz;
    float* Hy4 = Hx4 + hxsz;

    // Resolve device-global scratch addresses (host-side; graph-safe).
    float *EA, *EB, *HA, *HB;
    cudaGetSymbolAddress((void**)&EA, g_EpadA);
    cudaGetSymbolAddress((void**)&EB, g_EpadB);
    cudaGetSymbolAddress((void**)&HA, g_HyA);
    cudaGetSymbolAddress((void**)&HB, g_HyB);

    coef_kernel<<<1, 1>>>(beta, delta, gamma);

    const int eTot  = BB * ES * ES;
    const int hyTot = BB * NN * HYS;
    repackE_kernel <<<(eTot  + 255) / 256, 256>>>(E0);
    repackHy_kernel<<<(hyTot + 255) / 256, 256>>>(Hy0);

    dim3 blk(64, 4, 1);
    dim3 gE((NN + 1 + 127) / 128, (NN + 1 + 3) / 4, BB);   // 17 x 513 x 2
    dim3 gH((NN + 127) / 128, (NN + 3) / 4, BB);           // 16 x 512 x 2

    // step 1
    amper_kernel  <<<gE, blk>>>(EA, Hx0, HA, E2, EB);
    faraday_kernel<<<gH, blk>>>(EB, Hx0, HA, Hx2, Hy2, HB);
    // step 2
    amper_kernel  <<<gE, blk>>>(EB, Hx2, HB, E3, EA);
    faraday_kernel<<<gH, blk>>>(EA, Hx2, HB, Hx3, Hy3, HA);
    // step 3
    amper_kernel  <<<gE, blk>>>(EA, Hx3, HA, E4, EB);
    faraday_kernel<<<gH, blk>>>(EB, Hx3, HA, Hx4, Hy4, HB);
}